// round 5
// baseline (speedup 1.0000x reference)
#include <cuda_runtime.h>
#include <cuda_bf16.h>
#include <math.h>
#include <stdint.h>

#define NB 32
#define NK 17
#define HWPIX 4096

// ---------------- mma.sync / ldmatrix helpers ----------------
__device__ __forceinline__ uint32_t smem_to_u32(const void* p){
  uint32_t a; asm("{ .reg .u64 t; cvta.to.shared.u64 t, %1; cvt.u32.u64 %0, t; }" : "=r"(a) : "l"(p));
  return a;
}
__device__ __forceinline__ void ldsm4(uint32_t* r, uint32_t a){
  asm volatile("ldmatrix.sync.aligned.m8n8.x4.shared.b16 {%0,%1,%2,%3}, [%4];"
    : "=r"(r[0]), "=r"(r[1]), "=r"(r[2]), "=r"(r[3]) : "r"(a));
}
__device__ __forceinline__ void mma16816(float* d, const uint32_t* a, uint32_t b0, uint32_t b1){
  asm volatile("mma.sync.aligned.m16n8k16.row.col.f32.bf16.bf16.f32 "
    "{%0,%1,%2,%3}, {%4,%5,%6,%7}, {%8,%9}, {%0,%1,%2,%3};"
    : "+f"(d[0]), "+f"(d[1]), "+f"(d[2]), "+f"(d[3])
    : "r"(a[0]), "r"(a[1]), "r"(a[2]), "r"(a[3]), "r"(b0), "r"(b1));
}
__device__ __forceinline__ void cpa16_full(uint32_t d, const void* s){
  asm volatile("cp.async.cg.shared.global [%0], [%1], 16;" :: "r"(d), "l"(s));
}
__device__ __forceinline__ void cpa16z(uint32_t d, const void* s, int n){
  asm volatile("cp.async.cg.shared.global [%0], [%1], 16, %2;" :: "r"(d), "l"(s), "r"(n));
}
#define CP_COMMIT() asm volatile("cp.async.commit_group;" ::: "memory")
#define CP_WAIT(n)  asm volatile("cp.async.wait_group %0;" :: "n"(n) : "memory")
__device__ __forceinline__ uint32_t swz64(uint32_t o){ return o ^ ((o >> 3) & 0x30); }

// ---------------- static scratch ----------------
__device__ __align__(256) __nv_bfloat16 g_nh0[(size_t)NB*HWPIX*256];
__device__ __align__(256) __nv_bfloat16 g_nl0[(size_t)NB*HWPIX*256];
__device__ __align__(256) __nv_bfloat16 g_nh1[(size_t)NB*HWPIX*256];
__device__ __align__(256) __nv_bfloat16 g_nl1[(size_t)NB*HWPIX*256];
__device__ float g_f32a[(size_t)NB*256*HWPIX];   // heat branch staging
__device__ float g_f32b[(size_t)NB*256*HWPIX];   // offset branch staging
__device__ float g_f32c[(size_t)NB*128*HWPIX];   // var branch staging
// pre-swizzled hi/lo weights, chunk = (oct*8+icq)*3+ky, 3 taps x 4096 elems per chunk-half
// elem offsets: s1 0 | s2 589824 | h1 1179648 | o1 1769472 | v1 2359296
__device__ __align__(256) __nv_bfloat16 g_awh[2654208];
__device__ __align__(256) __nv_bfloat16 g_awl[2654208];
__device__ float g_cg[NB * NK * 2];

// ---------------- merged weight transform (single launch) ----------------
// layout per conv: [oct][icq][ky] chunk of 12288 elems = [tap(3)][128oc x 32ic SW64 4096]
__global__ void wtrans_all_kernel(const float* __restrict__ w0, const float* __restrict__ g0,
                                  const float* __restrict__ w1, const float* __restrict__ g1,
                                  const float* __restrict__ w2, const float* __restrict__ g2,
                                  const float* __restrict__ w3, const float* __restrict__ g3,
                                  const float* __restrict__ w4, const float* __restrict__ g4,
                                  __nv_bfloat16* __restrict__ awh, __nv_bfloat16* __restrict__ awl)
{
  int cid = blockIdx.y;
  const float* w; const float* g; int n; size_t ofs;
  switch (cid) {
    case 0: w = w0; g = g0; n = 589824; ofs = 0;       break;
    case 1: w = w1; g = g1; n = 589824; ofs = 589824;  break;
    case 2: w = w2; g = g2; n = 589824; ofs = 1179648; break;
    case 3: w = w3; g = g3; n = 589824; ofs = 1769472; break;
    default:w = w4; g = g4; n = 294912; ofs = 2359296; break;
  }
  int idx = blockIdx.x * 256 + threadIdx.x;
  if (idx >= n) return;
  int icr  = idx & 31;
  int ocr  = (idx >> 5) & 127;
  int rest = idx >> 12;
  int tapx = rest % 3;
  int ky   = (rest / 3) % 3;
  int icq  = (rest / 9) % 8;
  int oct  = rest / 72;
  int oc = (oct << 7) + ocr;
  int ic = (icq << 5) + icr;
  int t  = ky * 3 + tapx;
  float val = w[((size_t)(oc * 256 + ic)) * 9 + t] * g[oc] * rsqrtf(1.0f + 1e-5f);
  __nv_bfloat16 hi = __float2bfloat16(val);
  __nv_bfloat16 lo = __float2bfloat16(val - __bfloat162float(hi));
  uint32_t off = (ocr << 6) + (icr << 1);
  uint32_t sw = swz64(off);
  size_t dst = ofs + ((size_t)(((oct * 8 + icq) * 3 + ky) * 3 + tapx) << 12) + (sw >> 1);
  awh[dst] = hi; awl[dst] = lo;
}

// ---------------- x: NCHW f32 -> NHWC bf16 hi/lo ----------------
__global__ void transpose_split_kernel(const float* __restrict__ x,
                                       __nv_bfloat16* __restrict__ xh,
                                       __nv_bfloat16* __restrict__ xl)
{
  __shared__ float t[64][65];
  int b = blockIdx.z, icb = blockIdx.y, pb = blockIdx.x;
  int p0 = pb << 6, ic0 = icb << 6;
  int tid = threadIdx.x;
  int r = tid >> 6, c = tid & 63;
  const float* xp = x + ((size_t)b * 256 + ic0) * HWPIX + p0;
  #pragma unroll
  for (int k = 0; k < 16; k++) {
    int icl = (k << 2) + r;
    t[icl][c] = xp[(size_t)icl * HWPIX + c];
  }
  __syncthreads();
  #pragma unroll
  for (int k = 0; k < 16; k++) {
    int pl = (k << 2) + r;
    float v = t[c][pl];
    __nv_bfloat16 hi = __float2bfloat16(v);
    __nv_bfloat16 lo = __float2bfloat16(v - __bfloat162float(hi));
    size_t dst = (((size_t)b << 12) + p0 + pl) * 256 + ic0 + c;
    xh[dst] = hi; xl[dst] = lo;
  }
}

// ---------------- HMMA implicit 3x3 conv + BN(fold) + ReLU ----------------
// CTA: M=128 oc x N=256 px (4 rows), 512 thr / 16 warps, warp tile m32 x n64.
// 24 steps: icq(8) x ky(3); each step = 3 taps x k32 (one ky row of the 3x3).
// smem: A 2x48KB @0 ; B 2x50688 @98304. total 199680.
#define A_STAGE 49152
#define B_BASE  98304
#define B_STAGE 50688
#define B_HALF  25344
#define SMEM_CONV 199680

template<int MODE>  // 0: write NHWC bf16 hi/lo (OC=256) ; 1: write NCHW fp32
__global__ void __launch_bounds__(512, 1)
conv3_mma(const __nv_bfloat16* __restrict__ xh, const __nv_bfloat16* __restrict__ xl,
          const __nv_bfloat16* __restrict__ awh, const __nv_bfloat16* __restrict__ awl,
          const float* __restrict__ bias,
          __nv_bfloat16* __restrict__ yh, __nv_bfloat16* __restrict__ yl,
          float* __restrict__ yf, int OC)
{
  extern __shared__ char smem[];
  const uint32_t sb = smem_to_u32(smem);
  const int tid = threadIdx.x, wid = tid >> 5, lane = tid & 31;
  const int lr = lane & 15, lh = lane >> 4;
  const int b = blockIdx.z, oct = blockIdx.y, pt = blockIdx.x;
  const int p0 = pt << 8;
  const int y0 = pt << 2;
  const int wM = (wid & 3) << 5;
  const int wN = (wid >> 2) << 6;

  float acc[2][8][4];
  #pragma unroll
  for (int mt = 0; mt < 2; mt++)
    #pragma unroll
    for (int q = 0; q < 8; q++)
      #pragma unroll
      for (int r = 0; r < 4; r++) acc[mt][q][r] = 0.f;

  auto loadA = [&](int icq, int ky, int buf){
    uint32_t dst = sb + buf * A_STAGE;
    const char* ah = (const char*)(awh + ((size_t)((oct * 8 + icq) * 3 + ky) * 12288));
    const char* al = (const char*)(awl + ((size_t)((oct * 8 + icq) * 3 + ky) * 12288));
    #pragma unroll
    for (int i = 0; i < 3; i++) {
      int o16 = (tid + (i << 9)) << 4;       // 1536 x 16B = 24KB per half
      cpa16_full(dst + o16, ah + o16);
      cpa16_full(dst + 24576 + o16, al + o16);
    }
  };
  auto loadB = [&](int icq, int buf){
    uint32_t dst = sb + B_BASE + buf * B_STAGE;
    // halo: 6 rows (y0-1..y0+4) x 66 cols; 32 ic = 64B per px, SW64
    #pragma unroll
    for (int i = 0; i < 4; i++) {
      int q = tid + (i << 9);
      if (q < 1584) {
        int sct = q & 3;
        int pr  = q >> 2;
        int hr  = pr / 66, hc = pr % 66;
        int gy = y0 - 1 + hr, gx = hc - 1;
        bool v = ((unsigned)gy < 64u) && ((unsigned)gx < 64u);
        uint32_t dsw = swz64((uint32_t)((pr << 6) + (sct << 4)));
        size_t ge = v ? (((((size_t)b << 12) + (gy << 6) + gx) << 8) + (icq << 5) + (sct << 3)) : 0;
        cpa16z(dst + dsw, xh + ge, v ? 16 : 0);
        cpa16z(dst + B_HALF + dsw, xl + ge, v ? 16 : 0);
      }
    }
  };

  loadB(0, 0);
  loadA(0, 0, 0);
  CP_COMMIT();

  uint32_t arow[2];
  #pragma unroll
  for (int mt = 0; mt < 2; mt++) arow[mt] = (uint32_t)((wM + (mt << 4) + lr) << 6);

  for (int icq = 0; icq < 8; icq++) {
    #pragma unroll 1
    for (int ky = 0; ky < 3; ky++) {
      const int s = icq * 3 + ky;
      CP_WAIT(0);
      __syncthreads();
      if (s + 1 < 24) {
        int kyn = ky + 1, icqn = icq;
        if (kyn == 3) { kyn = 0; icqn = icq + 1; }
        loadA(icqn, kyn, (s + 1) & 1);
        if (kyn == 0) loadB(icqn, icqn & 1);
        CP_COMMIT();
      }

      const int dy = ky - 1;
      const uint32_t Ab = sb + (s & 1) * A_STAGE;
      const uint32_t Bb = sb + B_BASE + (icq & 1) * B_STAGE;

      #pragma unroll
      for (int tap = 0; tap < 3; tap++) {
        const int dx = tap - 1;
        uint32_t brow[4];
        #pragma unroll
        for (int j = 0; j < 4; j++) {
          int p = wN + (j << 4) + lr;
          int hy = (p >> 6) + 1 + dy;
          int hx = (p & 63) + 1 + dx;
          brow[j] = (uint32_t)((hy * 66 + hx) << 6);
        }
        const uint32_t Ath = Ab + tap * 8192;
        const uint32_t Atl = Ab + 24576 + tap * 8192;

        #pragma unroll
        for (int ks = 0; ks < 2; ks++) {
          const uint32_t cofs = (uint32_t)(((ks << 1) + lh) << 4);
          uint32_t ah[2][4], al[2][4], bh[4][4], bl[4][4];
          #pragma unroll
          for (int mt = 0; mt < 2; mt++) {
            uint32_t ao = swz64(arow[mt] + cofs);
            ldsm4(ah[mt], Ath + ao);
            ldsm4(al[mt], Atl + ao);
          }
          #pragma unroll
          for (int j = 0; j < 4; j++) {
            uint32_t bo = swz64(brow[j] + cofs);
            ldsm4(bh[j], Bb + bo);
            ldsm4(bl[j], Bb + B_HALF + bo);
          }
          #pragma unroll
          for (int mt = 0; mt < 2; mt++)
            #pragma unroll
            for (int j = 0; j < 4; j++)
              #pragma unroll
              for (int f = 0; f < 2; f++)
                mma16816(acc[mt][(j << 1) + f], ah[mt], bh[j][f], bh[j][2 + f]);
          #pragma unroll
          for (int mt = 0; mt < 2; mt++)
            #pragma unroll
            for (int j = 0; j < 4; j++)
              #pragma unroll
              for (int f = 0; f < 2; f++)
                mma16816(acc[mt][(j << 1) + f], ah[mt], bl[j][f], bl[j][2 + f]);
          #pragma unroll
          for (int mt = 0; mt < 2; mt++)
            #pragma unroll
            for (int j = 0; j < 4; j++)
              #pragma unroll
              for (int f = 0; f < 2; f++)
                mma16816(acc[mt][(j << 1) + f], al[mt], bh[j][f], bh[j][2 + f]);
        }
      }
    }
  }
  __syncthreads();

  // ---- epilogue ----
  if (MODE == 1) {
    #pragma unroll
    for (int mt = 0; mt < 2; mt++) {
      int ocl = wM + (mt << 4) + (lane >> 2);
      int oc = (oct << 7) + ocl;
      float b0 = bias[oc], b8 = bias[oc + 8];
      float* base0 = yf + (((size_t)b * OC + oc) << 12) + p0;
      #pragma unroll
      for (int j = 0; j < 4; j++)
        #pragma unroll
        for (int f = 0; f < 2; f++) {
          float* d = acc[mt][(j << 1) + f];
          int colL = wN + (j << 4) + (f << 3) + ((lane & 3) << 1);
          float2 v;
          v.x = fmaxf(d[0] + b0, 0.f); v.y = fmaxf(d[1] + b0, 0.f);
          *(float2*)(base0 + colL) = v;
          v.x = fmaxf(d[2] + b8, 0.f); v.y = fmaxf(d[3] + b8, 0.f);
          *(float2*)(base0 + (8 << 12) + colL) = v;
        }
    }
  } else {
    float* sm = (float*)smem;  // [256 px][132]
    #pragma unroll
    for (int mt = 0; mt < 2; mt++) {
      int ocl = wM + (mt << 4) + (lane >> 2);
      float b0 = bias[(oct << 7) + ocl], b8 = bias[(oct << 7) + ocl + 8];
      #pragma unroll
      for (int j = 0; j < 4; j++)
        #pragma unroll
        for (int f = 0; f < 2; f++) {
          float* d = acc[mt][(j << 1) + f];
          int colL = wN + (j << 4) + (f << 3) + ((lane & 3) << 1);
          sm[colL * 132 + ocl]           = fmaxf(d[0] + b0, 0.f);
          sm[(colL + 1) * 132 + ocl]     = fmaxf(d[1] + b0, 0.f);
          sm[colL * 132 + ocl + 8]       = fmaxf(d[2] + b8, 0.f);
          sm[(colL + 1) * 132 + ocl + 8] = fmaxf(d[3] + b8, 0.f);
        }
    }
    __syncthreads();
    int px = tid >> 1, oh = (tid & 1) << 6;
    const float* row = sm + px * 132 + oh;
    size_t gbase = (((size_t)b << 12) + p0 + px) * 256 + (oct << 7) + oh;
    #pragma unroll
    for (int j = 0; j < 64; j += 4) {
      float4 v = *(const float4*)(row + j);
      __nv_bfloat16 h0 = __float2bfloat16(v.x), h1 = __float2bfloat16(v.y);
      __nv_bfloat16 h2 = __float2bfloat16(v.z), h3 = __float2bfloat16(v.w);
      __nv_bfloat16 l0 = __float2bfloat16(v.x - __bfloat162float(h0));
      __nv_bfloat16 l1 = __float2bfloat16(v.y - __bfloat162float(h1));
      __nv_bfloat16 l2 = __float2bfloat16(v.z - __bfloat162float(h2));
      __nv_bfloat16 l3 = __float2bfloat16(v.w - __bfloat162float(h3));
      uint2 hv, lv;
      hv.x = (uint32_t)__bfloat16_as_ushort(h0) | ((uint32_t)__bfloat16_as_ushort(h1) << 16);
      hv.y = (uint32_t)__bfloat16_as_ushort(h2) | ((uint32_t)__bfloat16_as_ushort(h3) << 16);
      lv.x = (uint32_t)__bfloat16_as_ushort(l0) | ((uint32_t)__bfloat16_as_ushort(l1) << 16);
      lv.y = (uint32_t)__bfloat16_as_ushort(l2) | ((uint32_t)__bfloat16_as_ushort(l3) << 16);
      *(uint2*)(yh + gbase + j) = hv;
      *(uint2*)(yl + gbase + j) = lv;
    }
  }
}

// ---------------- 1x1 heads, soft-argmax, finalize (validated) ----------------
__device__ __forceinline__ float softplusf(float x){
  return fmaxf(x, 0.f) + log1pf(expf(-fabsf(x)));
}

template<int OC>
__global__ __launch_bounds__(256)
void conv1x1_kernel(const float* __restrict__ x, const float* __restrict__ w,
                    const float* __restrict__ bias, float* __restrict__ y,
                    int IC, int act)
{
  __shared__ float ws[OC * 256];
  int b = blockIdx.y;
  int tid = threadIdx.x;
  int n = OC * IC;
  for (int q = tid; q < n; q += 256) ws[q] = w[q];
  __syncthreads();
  int pix = blockIdx.x * 256 + tid;
  const float* xp = x + (size_t)b * IC * HWPIX + pix;
  float acc[OC];
  #pragma unroll
  for (int o = 0; o < OC; o++) acc[o] = bias[o];
  for (int ic = 0; ic < IC; ic += 4) {
    float x0 = xp[(size_t)ic * HWPIX];
    float x1 = xp[(size_t)(ic + 1) * HWPIX];
    float x2 = xp[(size_t)(ic + 2) * HWPIX];
    float x3 = xp[(size_t)(ic + 3) * HWPIX];
    #pragma unroll
    for (int o = 0; o < OC; o++) {
      float4 w4 = *(const float4*)&ws[o * IC + ic];
      acc[o] += w4.x * x0 + w4.y * x1 + w4.z * x2 + w4.w * x3;
    }
  }
  float* yp = y + ((size_t)b * OC) * HWPIX + pix;
  #pragma unroll
  for (int o = 0; o < OC; o++) {
    float v = acc[o];
    if (act) v = softplusf(v);
    yp[(size_t)o * HWPIX] = v;
  }
}

__global__ void softargmax_kernel(const float* __restrict__ heat, float* __restrict__ cg,
                                  float* __restrict__ scores)
{
  int bk = blockIdx.x;
  const float* h = heat + (size_t)bk * HWPIX;
  int tid = threadIdx.x;
  __shared__ float r0[256], r1[256], r2[256];

  float m = -3.4e38f;
  for (int i = tid; i < HWPIX; i += 256) m = fmaxf(m, h[i]);
  r0[tid] = m; __syncthreads();
  for (int s = 128; s > 0; s >>= 1) { if (tid < s) r0[tid] = fmaxf(r0[tid], r0[tid + s]); __syncthreads(); }
  float M = r0[0];
  __syncthreads();

  float s = 0.f, sx = 0.f, sy = 0.f;
  for (int i = tid; i < HWPIX; i += 256) {
    float e = expf(h[i] - M);
    s += e; sx += e * (float)(i & 63); sy += e * (float)(i >> 6);
  }
  r0[tid] = s; r1[tid] = sx; r2[tid] = sy; __syncthreads();
  for (int st = 128; st > 0; st >>= 1) {
    if (tid < st) { r0[tid] += r0[tid + st]; r1[tid] += r1[tid + st]; r2[tid] += r2[tid + st]; }
    __syncthreads();
  }
  if (tid == 0) {
    cg[bk * 2]     = r1[0] / r0[0];
    cg[bk * 2 + 1] = r2[0] / r0[0];
    scores[bk] = M;
  }
}

__global__ void finalize_kernel(const float* __restrict__ heat, const float* __restrict__ off,
                                const float* __restrict__ cg, const float* __restrict__ alpha_p,
                                const float* __restrict__ fusion_p, float* __restrict__ coords_out,
                                float* __restrict__ fw_out)
{
  int idx = blockIdx.x * blockDim.x + threadIdx.x;
  float fw = 1.f / (1.f + expf(-fusion_p[0]));
  if (idx == 0) fw_out[0] = fw;
  if (idx >= NB * NK) return;
  float a = 1.f / (1.f + expf(-alpha_p[0]));
  float cgx = cg[idx * 2], cgy = cg[idx * 2 + 1];
  const float* hm = heat + (size_t)idx * HWPIX;

  int px = (int)rintf(fminf(fmaxf(cgx, 0.f), 63.f));
  int py = (int)rintf(fminf(fmaxf(cgy, 0.f), 63.f));
  int xcc[5], ycc[5]; bool mx[5], my[5];
  #pragma unroll
  for (int d = 0; d < 5; d++) {
    int xv = px + d - 2; mx[d] = (xv >= 0 && xv < 64); xcc[d] = min(max(xv, 0), 63);
    int yv = py + d - 2; my[d] = (yv >= 0 && yv < 64); ycc[d] = min(max(yv, 0), 63);
  }
  float pv[25]; float m = -3.4e38f;
  #pragma unroll
  for (int i = 0; i < 5; i++)
    #pragma unroll
    for (int j = 0; j < 5; j++) {
      float v = -3.4e38f;
      if (my[i] && mx[j]) v = hm[ycc[i] * 64 + xcc[j]];
      pv[i * 5 + j] = v; m = fmaxf(m, v);
    }
  float s = 0.f, rx = 0.f, ry = 0.f;
  #pragma unroll
  for (int i = 0; i < 5; i++)
    #pragma unroll
    for (int j = 0; j < 5; j++) {
      float e = (my[i] && mx[j]) ? expf(pv[i * 5 + j] - m) : 0.f;
      s += e; rx += e * (float)xcc[j]; ry += e * (float)ycc[i];
    }
  rx /= s; ry /= s;

  float cx = a * cgx + (1.f - a) * rx;
  float cy = a * cgy + (1.f - a) * ry;

  float ix = fminf(fmaxf(cx, 0.f), 63.f);
  float iy = fminf(fmaxf(cy, 0.f), 63.f);
  float x0f = floorf(ix), y0f = floorf(iy);
  float wx = ix - x0f, wy = iy - y0f;
  int x0 = min(max((int)x0f, 0), 63); int x1 = min(x0 + 1, 63);
  int y0 = min(max((int)y0f, 0), 63); int y1 = min(y0 + 1, 63);
  const float* oc0 = off + (size_t)idx * 2 * HWPIX;
  const float* oc1 = oc0 + HWPIX;
  float v00 = oc0[y0 * 64 + x0], v01 = oc0[y0 * 64 + x1];
  float v10 = oc0[y1 * 64 + x0], v11 = oc0[y1 * 64 + x1];
  float s0 = (1.f - wy) * ((1.f - wx) * v00 + wx * v01) + wy * ((1.f - wx) * v10 + wx * v11);
  v00 = oc1[y0 * 64 + x0]; v01 = oc1[y0 * 64 + x1];
  v10 = oc1[y1 * 64 + x0]; v11 = oc1[y1 * 64 + x1];
  float s1 = (1.f - wy) * ((1.f - wx) * v00 + wx * v01) + wy * ((1.f - wx) * v10 + wx * v11);

  coords_out[idx * 2]     = cx + fw * s0;
  coords_out[idx * 2 + 1] = cy + fw * s1;
}

// ---------------- output layout ----------------
#define HEAT_OFS   0
#define OFF_OFS    2228224
#define VAR_OFS    6684672
#define FW_OFS     8912896
#define COORD_OFS  8912897
#define SCORE_OFS  8913985

#define AW_S1 0
#define AW_S2 589824
#define AW_H1 1179648
#define AW_O1 1769472
#define AW_V1 2359296

extern "C" void kernel_launch(void* const* d_in, const int* in_sizes, int n_in,
                              void* d_out, int out_size)
{
  const float* x    = (const float*)d_in[0];
  const float* w_s1 = (const float*)d_in[1];
  const float* g_s1 = (const float*)d_in[2];
  const float* b_s1 = (const float*)d_in[3];
  const float* w_s2 = (const float*)d_in[4];
  const float* g_s2 = (const float*)d_in[5];
  const float* b_s2 = (const float*)d_in[6];
  const float* w_h1 = (const float*)d_in[7];
  const float* g_h1 = (const float*)d_in[8];
  const float* b_h1 = (const float*)d_in[9];
  const float* w_h2 = (const float*)d_in[10];
  const float* c_h2 = (const float*)d_in[11];
  const float* w_o1 = (const float*)d_in[12];
  const float* g_o1 = (const float*)d_in[13];
  const float* b_o1 = (const float*)d_in[14];
  const float* w_o2 = (const float*)d_in[15];
  const float* c_o2 = (const float*)d_in[16];
  const float* w_v1 = (const float*)d_in[17];
  const float* g_v1 = (const float*)d_in[18];
  const float* b_v1 = (const float*)d_in[19];
  const float* w_v2 = (const float*)d_in[20];
  const float* c_v2 = (const float*)d_in[21];
  const float* alpha  = (const float*)d_in[22];
  const float* fusion = (const float*)d_in[23];

  float* out    = (float*)d_out;
  float* heat   = out + HEAT_OFS;
  float* offp   = out + OFF_OFS;
  float* varp   = out + VAR_OFS;
  float* fwp    = out + FW_OFS;
  float* coords = out + COORD_OFS;
  float* scores = out + SCORE_OFS;

  void *ph0, *pl0, *ph1, *pl1, *pfa, *pfb, *pfc, *pwh, *pwl, *pcg;
  cudaGetSymbolAddress(&ph0, g_nh0);
  cudaGetSymbolAddress(&pl0, g_nl0);
  cudaGetSymbolAddress(&ph1, g_nh1);
  cudaGetSymbolAddress(&pl1, g_nl1);
  cudaGetSymbolAddress(&pfa, g_f32a);
  cudaGetSymbolAddress(&pfb, g_f32b);
  cudaGetSymbolAddress(&pfc, g_f32c);
  cudaGetSymbolAddress(&pwh, g_awh);
  cudaGetSymbolAddress(&pwl, g_awl);
  cudaGetSymbolAddress(&pcg, g_cg);
  __nv_bfloat16* Ah = (__nv_bfloat16*)ph0;
  __nv_bfloat16* Al = (__nv_bfloat16*)pl0;
  __nv_bfloat16* Bh = (__nv_bfloat16*)ph1;
  __nv_bfloat16* Bl = (__nv_bfloat16*)pl1;
  float* F32a = (float*)pfa;
  float* F32b = (float*)pfb;
  float* F32c = (float*)pfc;
  __nv_bfloat16* awh = (__nv_bfloat16*)pwh;
  __nv_bfloat16* awl = (__nv_bfloat16*)pwl;
  float* cgp = (float*)pcg;

  cudaFuncSetAttribute(conv3_mma<0>, cudaFuncAttributeMaxDynamicSharedMemorySize, SMEM_CONV);
  cudaFuncSetAttribute(conv3_mma<1>, cudaFuncAttributeMaxDynamicSharedMemorySize, SMEM_CONV);

  // launch 0: merged weight transform
  wtrans_all_kernel<<<dim3(2304, 5), 256>>>(w_s1, g_s1, w_s2, g_s2, w_h1, g_h1,
                                            w_o1, g_o1, w_v1, g_v1, awh, awl);
  // launch 1: input transpose
  transpose_split_kernel<<<dim3(64, 4, NB), 256>>>(x, Ah, Al);
  // launches 2-6: convs (launch #5 = o1 conv gets profiled by ncu -s 5 -c 1)
  conv3_mma<0><<<dim3(16, 2, NB), 512, SMEM_CONV>>>(Ah, Al, awh + AW_S1, awl + AW_S1, b_s1, Bh, Bl, nullptr, 256);
  conv3_mma<0><<<dim3(16, 2, NB), 512, SMEM_CONV>>>(Bh, Bl, awh + AW_S2, awl + AW_S2, b_s2, Ah, Al, nullptr, 256);
  conv3_mma<1><<<dim3(16, 2, NB), 512, SMEM_CONV>>>(Ah, Al, awh + AW_H1, awl + AW_H1, b_h1, nullptr, nullptr, F32a, 256);
  conv3_mma<1><<<dim3(16, 2, NB), 512, SMEM_CONV>>>(Ah, Al, awh + AW_O1, awl + AW_O1, b_o1, nullptr, nullptr, F32b, 256);
  conv3_mma<1><<<dim3(16, 1, NB), 512, SMEM_CONV>>>(Ah, Al, awh + AW_V1, awl + AW_V1, b_v1, nullptr, nullptr, F32c, 128);
  // heads
  conv1x1_kernel<17><<<dim3(16, NB), 256>>>(F32a, w_h2, c_h2, heat, 256, 0);
  conv1x1_kernel<34><<<dim3(16, NB), 256>>>(F32b, w_o2, c_o2, offp, 256, 0);
  conv1x1_kernel<17><<<dim3(16, NB), 256>>>(F32c, w_v2, c_v2, varp, 128, 1);
  // epilogue
  softargmax_kernel<<<NB * NK, 256>>>(heat, cgp, scores);
  finalize_kernel<<<3, 256>>>(heat, offp, cgp, alpha, fusion, coords, fwp);

  (void)in_sizes; (void)n_in; (void)out_size;
}